// round 1
// baseline (speedup 1.0000x reference)
#include <cuda_runtime.h>
#include <math.h>

// ---- NSA hyperparameters (fixed for this problem) ----
#define S_LEN 2048
#define HQ 16
#define HK 2
#define GQA 8          // HQ / HK
#define D 128
#define KS 32
#define ST 16
#define SEL 64
#define TOPN 16
#define WIN 512
#define TBLK 127       // (S - KS)/ST + 1
#define NSEL 32        // S / SEL
#define SCALE 0.08838834764831845f  // 1/sqrt(128)
#define FULLMASK 0xffffffffu

// ---- scratch (static device memory; no allocations allowed) ----
__device__ float   g_cmp_k[HK][TBLK][D];
__device__ float   g_cmp_v[HK][TBLK][D];
__device__ float   g_cmp_o[S_LEN][HQ][D];     // 16 MB
__device__ unsigned g_sel_mask[HK][S_LEN];

__device__ __forceinline__ float warp_sum(float v) {
#pragma unroll
    for (int o = 16; o; o >>= 1) v += __shfl_xor_sync(FULLMASK, v, o);
    return v;
}

// ============================================================
// Kernel 1: compressed K/V blocks
// cmp_k[n][t][d] = sum_w k[t*ST+w][n][d] * w_cmp_k[w]
// ============================================================
__global__ void k_compress(const float* __restrict__ k,
                           const float* __restrict__ v,
                           const float* __restrict__ wck,
                           const float* __restrict__ wcv) {
    int t = blockIdx.x;
    int n = blockIdx.y;
    int d = threadIdx.x;
    float ak = 0.f, av = 0.f;
#pragma unroll
    for (int w = 0; w < KS; ++w) {
        int j = t * ST + w;
        size_t idx = ((size_t)j * HK + n) * D + d;
        float wk = wck[w], wv = wcv[w];
        ak += k[idx] * wk;
        av += v[idx] * wv;
    }
    g_cmp_k[n][t][d] = ak;
    g_cmp_v[n][t][d] = av;
}

// ============================================================
// Kernel 2: compressed attention + top-n block selection
// One block per query position s. 16 warps = 16 query heads.
// Each warp: scores vs <=127 compressed blocks, softmax, PV
// into g_cmp_o, plus per-selection-block probability sums.
// Warps 0/1 then do deterministic top-16 selection per hk.
// ============================================================
__global__ void __launch_bounds__(512) k_cmp_attn(const float* __restrict__ q) {
    int s = blockIdx.x;
    int tid = threadIdx.x;
    int h = tid >> 5;
    int lane = tid & 31;
    int n = h >> 3;

    __shared__ float ps[HQ][NSEL];   // per-head selection-block prob sums

    const float4 q4 = *reinterpret_cast<const float4*>(
        q + ((size_t)s * HQ + h) * D + 4 * lane);

    int Tvis = (s >= KS - 1) ? ((s - (KS - 1)) / ST + 1) : 0;

    float m = -INFINITY;
    float scv[4] = {0.f, 0.f, 0.f, 0.f};

    // ---- scores ----
#pragma unroll
    for (int c = 0; c < 4; ++c) {
        for (int tt = 0; tt < 32; ++tt) {
            int t = c * 32 + tt;
            if (t >= Tvis) break;                       // warp-uniform
            const float4 kk = *reinterpret_cast<const float4*>(&g_cmp_k[n][t][4 * lane]);
            float p = q4.x * kk.x + q4.y * kk.y + q4.z * kk.z + q4.w * kk.w;
            p = warp_sum(p) * SCALE;
            m = fmaxf(m, p);
            if (tt == lane) scv[c] = p;
        }
    }

    // ---- softmax ----
    float lsum = 0.f;
#pragma unroll
    for (int c = 0; c < 4; ++c) {
        int t = c * 32 + lane;
        float e = (t < Tvis) ? __expf(scv[c] - m) : 0.f;
        scv[c] = e;
        lsum += e;
    }
    lsum = warp_sum(lsum);
    float inv = (Tvis > 0) ? 1.f / lsum : 0.f;

    // ---- PV + selection-block prob sums ----
    float4 acc = {0.f, 0.f, 0.f, 0.f};
    float pslc = 0.f;   // lane holds sum for selection block == lane
#pragma unroll
    for (int c = 0; c < 4; ++c) {
        for (int tt = 0; tt < 32; ++tt) {
            int t = c * 32 + tt;
            if (t >= Tvis) break;
            float p = __shfl_sync(FULLMASK, scv[c], tt) * inv;
            const float4 vv = *reinterpret_cast<const float4*>(&g_cmp_v[n][t][4 * lane]);
            acc.x += p * vv.x; acc.y += p * vv.y;
            acc.z += p * vv.z; acc.w += p * vv.w;
            int mlo = t >> 2;                     // (t*16)/64
            if (mlo == lane) pslc += p;
            if ((t & 3) == 3 && (mlo + 1) == lane) pslc += p;  // block straddles
        }
    }
    *reinterpret_cast<float4*>(&g_cmp_o[s][h][4 * lane]) = acc;

    ps[h][lane] = pslc;
    __syncthreads();

    // ---- top-16 selection per hk (warps 0 and 1), deterministic order ----
    if (h < HK) {
        int nn = h;
        float sco = 0.f;
#pragma unroll
        for (int g = 0; g < GQA; ++g) sco += ps[nn * GQA + g][lane];
        int cur = s >> 6;   // s / SEL
        bool forced = (lane == 0) || (lane == cur);
        bool causal = (lane <= cur);
        float val = forced ? 1e30f : (causal ? sco : -1e30f);
        unsigned mask = 0;
        for (int it = 0; it < TOPN; ++it) {
            float bv = val;
            int bi = lane;
#pragma unroll
            for (int o = 16; o; o >>= 1) {
                float ov = __shfl_xor_sync(FULLMASK, bv, o);
                int oi = __shfl_xor_sync(FULLMASK, bi, o);
                if (ov > bv || (ov == bv && oi < bi)) { bv = ov; bi = oi; }
            }
            if (bv > -5e29f) mask |= (1u << bi);
            if (lane == bi) val = -INFINITY;
        }
        if (lane == 0) g_sel_mask[nn][s] = mask;
    }
}

// ============================================================
// Kernel 3: selected + windowed attention with shared scores,
// two online-softmax states, gated final combine.
// One block per (s, h); 4 warps split tokens; lanes over d.
// ============================================================
__global__ void __launch_bounds__(128) k_main_attn(const float* __restrict__ q,
                                                   const float* __restrict__ kg,
                                                   const float* __restrict__ vg,
                                                   const float* __restrict__ wg,
                                                   const float* __restrict__ bg,
                                                   float* __restrict__ out) {
    int s = blockIdx.x;
    int h = blockIdx.y;
    int tid = threadIdx.x;
    int wid = tid >> 5;
    int lane = tid & 31;
    int n = h >> 3;

    __shared__ float red_m[2][4], red_l[2][4];
    __shared__ float red_a[2][4][D];
    __shared__ float gsm[3];

    const float4 q4 = *reinterpret_cast<const float4*>(
        q + ((size_t)s * HQ + h) * D + 4 * lane);

    // gating (warp 0, overlaps with main loop of other warps)
    if (wid == 0) {
#pragma unroll
        for (int c = 0; c < 3; ++c) {
            float gp = q4.x * wg[(4 * lane + 0) * 3 + c]
                     + q4.y * wg[(4 * lane + 1) * 3 + c]
                     + q4.z * wg[(4 * lane + 2) * 3 + c]
                     + q4.w * wg[(4 * lane + 3) * 3 + c];
            gp = warp_sum(gp);
            if (lane == 0) gsm[c] = 1.f / (1.f + __expf(-(gp + bg[c])));
        }
    }

    unsigned mask = g_sel_mask[n][s];
    int cur = s >> 6;
    int winlo = (s > WIN) ? (s - WIN) : 0;

    float mS = -INFINITY, lS = 0.f; float4 aS = {0.f, 0.f, 0.f, 0.f};
    float mW = -INFINITY, lW = 0.f; float4 aW = {0.f, 0.f, 0.f, 0.f};

    for (int b = 0; b <= cur; ++b) {
        bool insel = (mask >> b) & 1u;
        int bst = b << 6;
        bool winblk = (bst + SEL - 1) >= winlo;
        if (!insel && !winblk) continue;
        int jend = min(bst + SEL - 1, s);
        for (int j = bst + wid; j <= jend; j += 4) {
            bool tw = (j >= winlo);                 // token in window
            if (!insel && !tw) continue;            // warp-uniform
            size_t kidx = ((size_t)j * HK + n) * D + 4 * lane;
            const float4 kk = *reinterpret_cast<const float4*>(kg + kidx);
            float sc = q4.x * kk.x + q4.y * kk.y + q4.z * kk.z + q4.w * kk.w;
            sc = warp_sum(sc) * SCALE;
            const float4 vv = *reinterpret_cast<const float4*>(vg + kidx);
            if (insel) {
                float nm = fmaxf(mS, sc);
                float al = __expf(mS - nm);
                float p  = __expf(sc - nm);
                lS = lS * al + p;
                aS.x = aS.x * al + p * vv.x; aS.y = aS.y * al + p * vv.y;
                aS.z = aS.z * al + p * vv.z; aS.w = aS.w * al + p * vv.w;
                mS = nm;
            }
            if (tw) {
                float nm = fmaxf(mW, sc);
                float al = __expf(mW - nm);
                float p  = __expf(sc - nm);
                lW = lW * al + p;
                aW.x = aW.x * al + p * vv.x; aW.y = aW.y * al + p * vv.y;
                aW.z = aW.z * al + p * vv.z; aW.w = aW.w * al + p * vv.w;
                mW = nm;
            }
        }
    }

    if (lane == 0) {
        red_m[0][wid] = mS; red_l[0][wid] = lS;
        red_m[1][wid] = mW; red_l[1][wid] = lW;
    }
    red_a[0][wid][4 * lane + 0] = aS.x; red_a[0][wid][4 * lane + 1] = aS.y;
    red_a[0][wid][4 * lane + 2] = aS.z; red_a[0][wid][4 * lane + 3] = aS.w;
    red_a[1][wid][4 * lane + 0] = aW.x; red_a[1][wid][4 * lane + 1] = aW.y;
    red_a[1][wid][4 * lane + 2] = aW.z; red_a[1][wid][4 * lane + 3] = aW.w;
    __syncthreads();

    int d = tid;   // 0..127
    float o01[2];
#pragma unroll
    for (int st = 0; st < 2; ++st) {
        float M = fmaxf(fmaxf(red_m[st][0], red_m[st][1]),
                        fmaxf(red_m[st][2], red_m[st][3]));
        float L = 0.f, O = 0.f;
#pragma unroll
        for (int w = 0; w < 4; ++w) {
            float e = __expf(red_m[st][w] - M);
            L += red_l[st][w] * e;
            O += red_a[st][w][d] * e;
        }
        o01[st] = O / L;
    }
    float c = g_cmp_o[s][h][d];
    out[((size_t)s * HQ + h) * D + d] = c * gsm[0] + o01[0] * gsm[1] + o01[1] * gsm[2];
}

// ============================================================
// launch
// Inputs (metadata order): q, k, v, w_cmp_k, w_cmp_v, w_gate, b_gate
// ============================================================
extern "C" void kernel_launch(void* const* d_in, const int* in_sizes, int n_in,
                              void* d_out, int out_size) {
    const float* q   = (const float*)d_in[0];
    const float* k   = (const float*)d_in[1];
    const float* v   = (const float*)d_in[2];
    const float* wck = (const float*)d_in[3];
    const float* wcv = (const float*)d_in[4];
    const float* wg  = (const float*)d_in[5];
    const float* bg  = (const float*)d_in[6];
    float* out = (float*)d_out;

    k_compress<<<dim3(TBLK, HK), D>>>(k, v, wck, wcv);
    k_cmp_attn<<<S_LEN, HQ * 32>>>(q);
    k_main_attn<<<dim3(S_LEN, HQ), 128>>>(q, k, v, wg, bg, out);
}

// round 2
// speedup vs baseline: 1.5630x; 1.5630x over previous
#include <cuda_runtime.h>
#include <math.h>

// ---- NSA hyperparameters (fixed for this problem) ----
#define S_LEN 2048
#define HQ 16
#define HK 2
#define GQA 8          // HQ / HK
#define D 128
#define KS 32
#define ST 16
#define SEL 64
#define TOPN 16
#define WIN 512
#define TBLK 127       // (S - KS)/ST + 1
#define NSEL 32        // S / SEL
#define SCALE 0.08838834764831845f  // 1/sqrt(128)
#define FULLMASK 0xffffffffu
#define KPITCH 132     // smem row pitch (floats): conflict-free for lane=row LDS.128

// ---- scratch (static device memory; no allocations allowed) ----
__device__ float   g_cmp_k[HK][TBLK][D];
__device__ float   g_cmp_v[HK][TBLK][D];
__device__ float   g_cmp_o[S_LEN][HQ][D];     // 16 MB
__device__ unsigned g_sel_mask[HK][S_LEN];

__device__ __forceinline__ float warp_sum(float v) {
#pragma unroll
    for (int o = 16; o; o >>= 1) v += __shfl_xor_sync(FULLMASK, v, o);
    return v;
}
__device__ __forceinline__ float warp_max(float v) {
#pragma unroll
    for (int o = 16; o; o >>= 1) v = fmaxf(v, __shfl_xor_sync(FULLMASK, v, o));
    return v;
}

// packed fp32x2 FMA / MUL (Blackwell; ptxas never auto-fuses these)
__device__ __forceinline__ float2 ffma2(float2 a, float2 b, float2 c) {
    unsigned long long au = *reinterpret_cast<unsigned long long*>(&a);
    unsigned long long bu = *reinterpret_cast<unsigned long long*>(&b);
    unsigned long long cu = *reinterpret_cast<unsigned long long*>(&c);
    unsigned long long du;
    asm("fma.rn.f32x2 %0, %1, %2, %3;" : "=l"(du) : "l"(au), "l"(bu), "l"(cu));
    return *reinterpret_cast<float2*>(&du);
}
__device__ __forceinline__ float2 fmul2(float2 a, float2 b) {
    unsigned long long au = *reinterpret_cast<unsigned long long*>(&a);
    unsigned long long bu = *reinterpret_cast<unsigned long long*>(&b);
    unsigned long long du;
    asm("mul.rn.f32x2 %0, %1, %2;" : "=l"(du) : "l"(au), "l"(bu));
    return *reinterpret_cast<float2*>(&du);
}

// ============================================================
// Kernel 1: compressed K/V blocks
// ============================================================
__global__ void k_compress(const float* __restrict__ k,
                           const float* __restrict__ v,
                           const float* __restrict__ wck,
                           const float* __restrict__ wcv) {
    int t = blockIdx.x;
    int n = blockIdx.y;
    int d = threadIdx.x;
    float ak = 0.f, av = 0.f;
#pragma unroll
    for (int w = 0; w < KS; ++w) {
        int j = t * ST + w;
        size_t idx = ((size_t)j * HK + n) * D + d;
        float wk = wck[w], wv = wcv[w];
        ak += k[idx] * wk;
        av += v[idx] * wv;
    }
    g_cmp_k[n][t][d] = ak;
    g_cmp_v[n][t][d] = av;
}

// ============================================================
// Kernel 2: compressed attention + top-n block selection
// (unchanged from round 1 — known correct, minor cost)
// ============================================================
__global__ void __launch_bounds__(512) k_cmp_attn(const float* __restrict__ q) {
    int s = blockIdx.x;
    int tid = threadIdx.x;
    int h = tid >> 5;
    int lane = tid & 31;
    int n = h >> 3;

    __shared__ float ps[HQ][NSEL];

    const float4 q4 = *reinterpret_cast<const float4*>(
        q + ((size_t)s * HQ + h) * D + 4 * lane);

    int Tvis = (s >= KS - 1) ? ((s - (KS - 1)) / ST + 1) : 0;

    float m = -INFINITY;
    float scv[4] = {0.f, 0.f, 0.f, 0.f};

#pragma unroll
    for (int c = 0; c < 4; ++c) {
        for (int tt = 0; tt < 32; ++tt) {
            int t = c * 32 + tt;
            if (t >= Tvis) break;
            const float4 kk = *reinterpret_cast<const float4*>(&g_cmp_k[n][t][4 * lane]);
            float p = q4.x * kk.x + q4.y * kk.y + q4.z * kk.z + q4.w * kk.w;
            p = warp_sum(p) * SCALE;
            m = fmaxf(m, p);
            if (tt == lane) scv[c] = p;
        }
    }

    float lsum = 0.f;
#pragma unroll
    for (int c = 0; c < 4; ++c) {
        int t = c * 32 + lane;
        float e = (t < Tvis) ? __expf(scv[c] - m) : 0.f;
        scv[c] = e;
        lsum += e;
    }
    lsum = warp_sum(lsum);
    float inv = (Tvis > 0) ? 1.f / lsum : 0.f;

    float4 acc = {0.f, 0.f, 0.f, 0.f};
    float pslc = 0.f;
#pragma unroll
    for (int c = 0; c < 4; ++c) {
        for (int tt = 0; tt < 32; ++tt) {
            int t = c * 32 + tt;
            if (t >= Tvis) break;
            float p = __shfl_sync(FULLMASK, scv[c], tt) * inv;
            const float4 vv = *reinterpret_cast<const float4*>(&g_cmp_v[n][t][4 * lane]);
            acc.x += p * vv.x; acc.y += p * vv.y;
            acc.z += p * vv.z; acc.w += p * vv.w;
            int mlo = t >> 2;
            if (mlo == lane) pslc += p;
            if ((t & 3) == 3 && (mlo + 1) == lane) pslc += p;
        }
    }
    *reinterpret_cast<float4*>(&g_cmp_o[s][h][4 * lane]) = acc;

    ps[h][lane] = pslc;
    __syncthreads();

    if (h < HK) {
        int nn = h;
        float sco = 0.f;
#pragma unroll
        for (int g = 0; g < GQA; ++g) sco += ps[nn * GQA + g][lane];
        int cur = s >> 6;
        bool forced = (lane == 0) || (lane == cur);
        bool causal = (lane <= cur);
        float val = forced ? 1e30f : (causal ? sco : -1e30f);
        unsigned mask = 0;
        for (int it = 0; it < TOPN; ++it) {
            float bv = val;
            int bi = lane;
#pragma unroll
            for (int o = 16; o; o >>= 1) {
                float ov = __shfl_xor_sync(FULLMASK, bv, o);
                int oi = __shfl_xor_sync(FULLMASK, bi, o);
                if (ov > bv || (ov == bv && oi < bi)) { bv = ov; bi = oi; }
            }
            if (bv > -5e29f) mask |= (1u << bi);
            if (lane == bi) val = -INFINITY;
        }
        if (lane == 0) g_sel_mask[nn][s] = mask;
    }
}

// ============================================================
// Kernel 3: selected + window attention, restructured.
// Block = (s, kv-head n); 8 warps = 8 GQA heads.
// K/V staged to smem in 32-token tiles shared by all heads.
// Lane = token for scores (full 128-d dot, no warp reduction),
// lane = d-quad for PV. Two online-softmax states; packed
// fma.rn.f32x2 throughout; gated combine at the end.
// ============================================================
__global__ void __launch_bounds__(256) k_main_attn(const float* __restrict__ q,
                                                   const float* __restrict__ kg,
                                                   const float* __restrict__ vg,
                                                   const float* __restrict__ wg,
                                                   const float* __restrict__ bg,
                                                   float* __restrict__ out) {
    int s = S_LEN - 1 - blockIdx.x;     // long blocks first
    int n = blockIdx.y;
    int tid = threadIdx.x;
    int wid = tid >> 5;
    int lane = tid & 31;
    int h = n * GQA + wid;

    __shared__ float qsm[GQA][D];
    __shared__ float ksm[32][KPITCH];
    __shared__ float vsm[32][KPITCH];

    const float4 q4 = *reinterpret_cast<const float4*>(
        q + ((size_t)s * HQ + h) * D + 4 * lane);
    *reinterpret_cast<float4*>(&qsm[wid][4 * lane]) = q4;

    // gates (all lanes end with the value via butterfly sum)
    float gte[3];
#pragma unroll
    for (int c = 0; c < 3; ++c) {
        float gp = q4.x * wg[(4 * lane + 0) * 3 + c]
                 + q4.y * wg[(4 * lane + 1) * 3 + c]
                 + q4.z * wg[(4 * lane + 2) * 3 + c]
                 + q4.w * wg[(4 * lane + 3) * 3 + c];
        gp = warp_sum(gp) + bg[c];
        gte[c] = 1.f / (1.f + __expf(-gp));
    }

    unsigned mask = g_sel_mask[n][s];
    int cur = s >> 6;
    int winlo = (s > WIN) ? (s - WIN) : 0;

    float mS = -INFINITY, lS = 0.f;
    float mW = -INFINITY, lW = 0.f;
    float2 aS0 = {0.f, 0.f}, aS1 = {0.f, 0.f};
    float2 aW0 = {0.f, 0.f}, aW1 = {0.f, 0.f};

    for (int b = 0; b <= cur; ++b) {
        bool insel = (mask >> b) & 1u;
        if (!insel && ((b + 1) << 6) <= winlo) continue;   // no window overlap
        for (int half = 0; half < 2; ++half) {
            int t0 = (b << 6) + half * 32;
            if (t0 > s) break;
            bool tile_win = (t0 + 31) >= winlo;
            if (!insel && !tile_win) continue;

            // ---- stage tile (block-uniform control flow) ----
            __syncthreads();
            for (int u = tid; u < 32 * 32; u += 256) {
                int t = u >> 5, d4 = u & 31;
                int jj = t0 + t; if (jj > S_LEN - 1) jj = S_LEN - 1;
                size_t gidx = ((size_t)jj * HK + n) * D + d4 * 4;
                *reinterpret_cast<float4*>(&ksm[t][d4 * 4]) =
                    *reinterpret_cast<const float4*>(kg + gidx);
                *reinterpret_cast<float4*>(&vsm[t][d4 * 4]) =
                    *reinterpret_cast<const float4*>(vg + gidx);
            }
            __syncthreads();

            // ---- score: lane = token ----
            int j = t0 + lane;
            bool vT = (j <= s);
            bool vW = vT && (j >= winlo);

            float2 a0 = {0.f, 0.f}, a1 = {0.f, 0.f};
#pragma unroll
            for (int d4 = 0; d4 < 32; ++d4) {
                float4 qq = *reinterpret_cast<const float4*>(&qsm[wid][d4 * 4]);
                float4 kk = *reinterpret_cast<const float4*>(&ksm[lane][d4 * 4]);
                float2 qa = {qq.x, qq.y}, qb = {qq.z, qq.w};
                float2 ka = {kk.x, kk.y}, kb = {kk.z, kk.w};
                a0 = ffma2(qa, ka, a0);
                a1 = ffma2(qb, kb, a1);
            }
            float sc = (a0.x + a0.y + a1.x + a1.y) * SCALE;

            float pS = 0.f, pW = 0.f;
            if (insel) {
                float tm = warp_max(vT ? sc : -INFINITY);
                float nm = fmaxf(mS, tm);
                float al = __expf(mS - nm);
                pS = vT ? __expf(sc - nm) : 0.f;
                mS = nm;
                lS = lS * al + pS;
                float2 al2 = {al, al};
                aS0 = fmul2(aS0, al2); aS1 = fmul2(aS1, al2);
            }
            if (tile_win) {
                float tm = warp_max(vW ? sc : -INFINITY);
                float nm = fmaxf(mW, tm);
                float al = __expf(mW - nm);
                pW = vW ? __expf(sc - nm) : 0.f;
                mW = nm;
                lW = lW * al + pW;
                float2 al2 = {al, al};
                aW0 = fmul2(aW0, al2); aW1 = fmul2(aW1, al2);
            }

            // ---- PV: lane = d-quad ----
            if (insel && tile_win) {
#pragma unroll
                for (int t = 0; t < 32; ++t) {
                    float pSt = __shfl_sync(FULLMASK, pS, t);
                    float pWt = __shfl_sync(FULLMASK, pW, t);
                    float4 vv = *reinterpret_cast<const float4*>(&vsm[t][4 * lane]);
                    float2 va = {vv.x, vv.y}, vb = {vv.z, vv.w};
                    float2 ps2 = {pSt, pSt}, pw2 = {pWt, pWt};
                    aS0 = ffma2(ps2, va, aS0); aS1 = ffma2(ps2, vb, aS1);
                    aW0 = ffma2(pw2, va, aW0); aW1 = ffma2(pw2, vb, aW1);
                }
            } else if (insel) {
#pragma unroll
                for (int t = 0; t < 32; ++t) {
                    float pSt = __shfl_sync(FULLMASK, pS, t);
                    float4 vv = *reinterpret_cast<const float4*>(&vsm[t][4 * lane]);
                    float2 va = {vv.x, vv.y}, vb = {vv.z, vv.w};
                    float2 ps2 = {pSt, pSt};
                    aS0 = ffma2(ps2, va, aS0); aS1 = ffma2(ps2, vb, aS1);
                }
            } else {
#pragma unroll
                for (int t = 0; t < 32; ++t) {
                    float pWt = __shfl_sync(FULLMASK, pW, t);
                    float4 vv = *reinterpret_cast<const float4*>(&vsm[t][4 * lane]);
                    float2 va = {vv.x, vv.y}, vb = {vv.z, vv.w};
                    float2 pw2 = {pWt, pWt};
                    aW0 = ffma2(pw2, va, aW0); aW1 = ffma2(pw2, vb, aW1);
                }
            }
        }
    }

    // ---- finalize ----
    float invS = 1.f / warp_sum(lS);
    float invW = 1.f / warp_sum(lW);
    const float4 c4 = *reinterpret_cast<const float4*>(&g_cmp_o[s][h][4 * lane]);
    float4 o4;
    o4.x = c4.x * gte[0] + aS0.x * invS * gte[1] + aW0.x * invW * gte[2];
    o4.y = c4.y * gte[0] + aS0.y * invS * gte[1] + aW0.y * invW * gte[2];
    o4.z = c4.z * gte[0] + aS1.x * invS * gte[1] + aW1.x * invW * gte[2];
    o4.w = c4.w * gte[0] + aS1.y * invS * gte[1] + aW1.y * invW * gte[2];
    *reinterpret_cast<float4*>(out + ((size_t)s * HQ + h) * D + 4 * lane) = o4;
}

// ============================================================
// launch
// Inputs (metadata order): q, k, v, w_cmp_k, w_cmp_v, w_gate, b_gate
// ============================================================
extern "C" void kernel_launch(void* const* d_in, const int* in_sizes, int n_in,
                              void* d_out, int out_size) {
    const float* q   = (const float*)d_in[0];
    const float* k   = (const float*)d_in[1];
    const float* v   = (const float*)d_in[2];
    const float* wck = (const float*)d_in[3];
    const float* wcv = (const float*)d_in[4];
    const float* wg  = (const float*)d_in[5];
    const float* bg  = (const float*)d_in[6];
    float* out = (float*)d_out;

    k_compress<<<dim3(TBLK, HK), D>>>(k, v, wck, wcv);
    k_cmp_attn<<<S_LEN, HQ * 32>>>(q);
    k_main_attn<<<dim3(S_LEN, HK), 256>>>(q, k, v, wg, bg, out);
}

// round 3
// speedup vs baseline: 1.5720x; 1.0057x over previous
#include <cuda_runtime.h>
#include <math.h>

// ---- NSA hyperparameters (fixed for this problem) ----
#define S_LEN 2048
#define HQ 16
#define HK 2
#define GQA 8          // HQ / HK
#define D 128
#define KS 32
#define ST 16
#define SEL 64
#define TOPN 16
#define WIN 512
#define TBLK 127       // (S - KS)/ST + 1
#define NSEL 32        // S / SEL
#define SCALE 0.08838834764831845f  // 1/sqrt(128)
#define FULLMASK 0xffffffffu
#define KPITCH 132     // smem row pitch (floats): conflict-free for lane=row LDS.128

// ---- scratch (static device memory; no allocations allowed) ----
__device__ float   g_cmp_k[HK][TBLK][D];
__device__ float   g_cmp_v[HK][TBLK][D];
__device__ float   g_cmp_o[S_LEN][HQ][D];     // 16 MB
__device__ unsigned g_sel_mask[HK][S_LEN];

__device__ __forceinline__ float warp_sum(float v) {
#pragma unroll
    for (int o = 16; o; o >>= 1) v += __shfl_xor_sync(FULLMASK, v, o);
    return v;
}
__device__ __forceinline__ float warp_max(float v) {
#pragma unroll
    for (int o = 16; o; o >>= 1) v = fmaxf(v, __shfl_xor_sync(FULLMASK, v, o));
    return v;
}

// packed fp32x2 FMA / MUL (Blackwell; ptxas never auto-fuses these)
__device__ __forceinline__ float2 ffma2(float2 a, float2 b, float2 c) {
    unsigned long long au = *reinterpret_cast<unsigned long long*>(&a);
    unsigned long long bu = *reinterpret_cast<unsigned long long*>(&b);
    unsigned long long cu = *reinterpret_cast<unsigned long long*>(&c);
    unsigned long long du;
    asm("fma.rn.f32x2 %0, %1, %2, %3;" : "=l"(du) : "l"(au), "l"(bu), "l"(cu));
    return *reinterpret_cast<float2*>(&du);
}
__device__ __forceinline__ float2 fmul2(float2 a, float2 b) {
    unsigned long long au = *reinterpret_cast<unsigned long long*>(&a);
    unsigned long long bu = *reinterpret_cast<unsigned long long*>(&b);
    unsigned long long du;
    asm("mul.rn.f32x2 %0, %1, %2;" : "=l"(du) : "l"(au), "l"(bu));
    return *reinterpret_cast<float2*>(&du);
}

// ============================================================
// Kernel 1: compressed K/V blocks
// ============================================================
__global__ void k_compress(const float* __restrict__ k,
                           const float* __restrict__ v,
                           const float* __restrict__ wck,
                           const float* __restrict__ wcv) {
    int t = blockIdx.x;
    int n = blockIdx.y;
    int d = threadIdx.x;
    float ak = 0.f, av = 0.f;
#pragma unroll
    for (int w = 0; w < KS; ++w) {
        int j = t * ST + w;
        size_t idx = ((size_t)j * HK + n) * D + d;
        float wk = wck[w], wv = wcv[w];
        ak += k[idx] * wk;
        av += v[idx] * wv;
    }
    g_cmp_k[n][t][d] = ak;
    g_cmp_v[n][t][d] = av;
}

// ============================================================
// Kernel 2: compressed attention + top-n block selection
// ============================================================
__global__ void __launch_bounds__(512) k_cmp_attn(const float* __restrict__ q) {
    int s = blockIdx.x;
    int tid = threadIdx.x;
    int h = tid >> 5;
    int lane = tid & 31;
    int n = h >> 3;

    __shared__ float ps[HQ][NSEL];

    const float4 q4 = *reinterpret_cast<const float4*>(
        q + ((size_t)s * HQ + h) * D + 4 * lane);

    int Tvis = (s >= KS - 1) ? ((s - (KS - 1)) / ST + 1) : 0;

    float m = -INFINITY;
    float scv[4] = {0.f, 0.f, 0.f, 0.f};

#pragma unroll
    for (int c = 0; c < 4; ++c) {
        for (int tt = 0; tt < 32; ++tt) {
            int t = c * 32 + tt;
            if (t >= Tvis) break;
            const float4 kk = *reinterpret_cast<const float4*>(&g_cmp_k[n][t][4 * lane]);
            float p = q4.x * kk.x + q4.y * kk.y + q4.z * kk.z + q4.w * kk.w;
            p = warp_sum(p) * SCALE;
            m = fmaxf(m, p);
            if (tt == lane) scv[c] = p;
        }
    }

    float lsum = 0.f;
#pragma unroll
    for (int c = 0; c < 4; ++c) {
        int t = c * 32 + lane;
        float e = (t < Tvis) ? __expf(scv[c] - m) : 0.f;
        scv[c] = e;
        lsum += e;
    }
    lsum = warp_sum(lsum);
    float inv = (Tvis > 0) ? 1.f / lsum : 0.f;

    float4 acc = {0.f, 0.f, 0.f, 0.f};
    float pslc = 0.f;
#pragma unroll
    for (int c = 0; c < 4; ++c) {
        for (int tt = 0; tt < 32; ++tt) {
            int t = c * 32 + tt;
            if (t >= Tvis) break;
            float p = __shfl_sync(FULLMASK, scv[c], tt) * inv;
            const float4 vv = *reinterpret_cast<const float4*>(&g_cmp_v[n][t][4 * lane]);
            acc.x += p * vv.x; acc.y += p * vv.y;
            acc.z += p * vv.z; acc.w += p * vv.w;
            int mlo = t >> 2;
            if (mlo == lane) pslc += p;
            if ((t & 3) == 3 && (mlo + 1) == lane) pslc += p;
        }
    }
    *reinterpret_cast<float4*>(&g_cmp_o[s][h][4 * lane]) = acc;

    ps[h][lane] = pslc;
    __syncthreads();

    if (h < HK) {
        int nn = h;
        float sco = 0.f;
#pragma unroll
        for (int g = 0; g < GQA; ++g) sco += ps[nn * GQA + g][lane];
        int cur = s >> 6;
        bool forced = (lane == 0) || (lane == cur);
        bool causal = (lane <= cur);
        float val = forced ? 1e30f : (causal ? sco : -1e30f);
        unsigned mask = 0;
        for (int it = 0; it < TOPN; ++it) {
            float bv = val;
            int bi = lane;
#pragma unroll
            for (int o = 16; o; o >>= 1) {
                float ov = __shfl_xor_sync(FULLMASK, bv, o);
                int oi = __shfl_xor_sync(FULLMASK, bi, o);
                if (ov > bv || (ov == bv && oi < bi)) { bv = ov; bi = oi; }
            }
            if (bv > -5e29f) mask |= (1u << bi);
            if (lane == bi) val = -INFINITY;
        }
        if (lane == 0) g_sel_mask[nn][s] = mask;
    }
}

// ============================================================
// Kernel 3: selected + window attention, software-pipelined.
// Block = (s, kv-head n); 8 warps = 8 GQA heads.
// Tile list precomputed; K/V of tile i+1 prefetched into
// registers (LDG) while tile i computes from smem.
// Lane = token for scores, lane = d-quad for PV.
// Dual tiles share one exp per token (pW = pS * exp(mS-mW)).
// ============================================================
__global__ void __launch_bounds__(256) k_main_attn(const float* __restrict__ q,
                                                   const float* __restrict__ kg,
                                                   const float* __restrict__ vg,
                                                   const float* __restrict__ wg,
                                                   const float* __restrict__ bg,
                                                   float* __restrict__ out) {
    int s = S_LEN - 1 - blockIdx.x;     // long blocks first
    int n = blockIdx.y;
    int tid = threadIdx.x;
    int wid = tid >> 5;
    int lane = tid & 31;
    int h = n * GQA + wid;

    __shared__ float qsm[GQA][D];
    __shared__ float ksm[32][KPITCH];
    __shared__ float vsm[32][KPITCH];
    __shared__ float2 psm[GQA][32];
    __shared__ int tlist[72];
    __shared__ int tcount;

    const float4 q4 = *reinterpret_cast<const float4*>(
        q + ((size_t)s * HQ + h) * D + 4 * lane);
    *reinterpret_cast<float4*>(&qsm[wid][4 * lane]) = q4;

    int cur = s >> 6;
    int winlo = (s > WIN) ? (s - WIN) : 0;

    // ---- build tile list (thread 0) ----
    if (tid == 0) {
        unsigned mk = g_sel_mask[n][s];
        int c = 0;
        for (int b = 0; b <= cur; ++b) {
            int insel = (mk >> b) & 1;
            for (int half = 0; half < 2; ++half) {
                int t0 = (b << 6) + half * 32;
                if (t0 > s) break;
                int twin = ((t0 + 31) >= winlo) ? 1 : 0;
                if (insel | twin) tlist[c++] = t0 | (insel << 12) | (twin << 13);
            }
        }
        tcount = c;
    }

    // gates (overlap with list build)
    float gte[3];
#pragma unroll
    for (int c = 0; c < 3; ++c) {
        float gp = q4.x * wg[(4 * lane + 0) * 3 + c]
                 + q4.y * wg[(4 * lane + 1) * 3 + c]
                 + q4.z * wg[(4 * lane + 2) * 3 + c]
                 + q4.w * wg[(4 * lane + 3) * 3 + c];
        gp = warp_sum(gp) + bg[c];
        gte[c] = 1.f / (1.f + __expf(-gp));
    }
    __syncthreads();

    int n_t = tcount;

    float mS = -INFINITY, lS = 0.f;
    float mW = -INFINITY, lW = 0.f;
    float2 aS0 = {0.f, 0.f}, aS1 = {0.f, 0.f};
    float2 aW0 = {0.f, 0.f}, aW1 = {0.f, 0.f};

    // staging geometry: thread handles rows wid, wid+8, wid+16, wid+24; col = lane quad
    int st_t[4];
#pragma unroll
    for (int r = 0; r < 4; ++r) st_t[r] = wid + 8 * r;

    float4 pk[4], pv[4];
    // prefetch tile 0
    if (n_t > 0) {
        int t0 = tlist[0] & 0xfff;
#pragma unroll
        for (int r = 0; r < 4; ++r) {
            size_t gi = ((size_t)(t0 + st_t[r]) * HK + n) * D + 4 * lane;
            pk[r] = *reinterpret_cast<const float4*>(kg + gi);
            pv[r] = *reinterpret_cast<const float4*>(vg + gi);
        }
    }

    for (int i = 0; i < n_t; ++i) {
        if (i > 0) __syncthreads();   // smem free (everyone done with tile i-1)
        // store prefetched tile i
#pragma unroll
        for (int r = 0; r < 4; ++r) {
            *reinterpret_cast<float4*>(&ksm[st_t[r]][4 * lane]) = pk[r];
            *reinterpret_cast<float4*>(&vsm[st_t[r]][4 * lane]) = pv[r];
        }
        // issue prefetch for tile i+1
        if (i + 1 < n_t) {
            int t0n = tlist[i + 1] & 0xfff;
#pragma unroll
            for (int r = 0; r < 4; ++r) {
                size_t gi = ((size_t)(t0n + st_t[r]) * HK + n) * D + 4 * lane;
                pk[r] = *reinterpret_cast<const float4*>(kg + gi);
                pv[r] = *reinterpret_cast<const float4*>(vg + gi);
            }
        }
        __syncthreads();              // tile i visible

        int e = tlist[i];
        int t0 = e & 0xfff;
        bool insel = (e >> 12) & 1;
        bool twin  = (e >> 13) & 1;

        int j = t0 + lane;
        bool vT = (j <= s);
        bool vW = vT && (j >= winlo);

        // ---- score: lane = token, 4 independent chains ----
        float2 c0 = {0.f, 0.f}, c1 = {0.f, 0.f}, c2 = {0.f, 0.f}, c3 = {0.f, 0.f};
#pragma unroll
        for (int d4 = 0; d4 < 32; d4 += 2) {
            float4 qq = *reinterpret_cast<const float4*>(&qsm[wid][d4 * 4]);
            float4 kk = *reinterpret_cast<const float4*>(&ksm[lane][d4 * 4]);
            c0 = ffma2({qq.x, qq.y}, {kk.x, kk.y}, c0);
            c1 = ffma2({qq.z, qq.w}, {kk.z, kk.w}, c1);
            float4 qq2 = *reinterpret_cast<const float4*>(&qsm[wid][(d4 + 1) * 4]);
            float4 kk2 = *reinterpret_cast<const float4*>(&ksm[lane][(d4 + 1) * 4]);
            c2 = ffma2({qq2.x, qq2.y}, {kk2.x, kk2.y}, c2);
            c3 = ffma2({qq2.z, qq2.w}, {kk2.z, kk2.w}, c3);
        }
        float sc = ((c0.x + c0.y) + (c1.x + c1.y) + (c2.x + c2.y) + (c3.x + c3.y)) * SCALE;

        // ---- online softmax updates ----
        float2 p2 = {0.f, 0.f};
        if (insel) {
            float tm = warp_max(vT ? sc : -INFINITY);
            float nm = fmaxf(mS, tm);
            float al = __expf(mS - nm);
            float pS = vT ? __expf(sc - nm) : 0.f;
            mS = nm;
            lS = lS * al + pS;
            float2 al2 = {al, al};
            aS0 = fmul2(aS0, al2); aS1 = fmul2(aS1, al2);
            p2.x = pS;
        }
        if (twin) {
            float tm = warp_max(vW ? sc : -INFINITY);
            float nm = fmaxf(mW, tm);
            float al = __expf(mW - nm);
            float pW;
            if (insel) {
                float cw = __expf(mS - nm);      // uniform: mS already updated
                pW = vW ? p2.x * cw : 0.f;
            } else {
                pW = vW ? __expf(sc - nm) : 0.f;
            }
            mW = nm;
            lW = lW * al + pW;
            float2 al2 = {al, al};
            aW0 = fmul2(aW0, al2); aW1 = fmul2(aW1, al2);
            p2.y = pW;
        }
        psm[wid][lane] = p2;
        __syncwarp();

        // ---- PV: lane = d-quad ----
        if (insel && twin) {
#pragma unroll
            for (int t = 0; t < 32; ++t) {
                float2 p = psm[wid][t];
                float4 vv = *reinterpret_cast<const float4*>(&vsm[t][4 * lane]);
                float2 va = {vv.x, vv.y}, vb = {vv.z, vv.w};
                float2 px = {p.x, p.x}, py = {p.y, p.y};
                aS0 = ffma2(px, va, aS0); aS1 = ffma2(px, vb, aS1);
                aW0 = ffma2(py, va, aW0); aW1 = ffma2(py, vb, aW1);
            }
        } else if (insel) {
#pragma unroll
            for (int t = 0; t < 32; ++t) {
                float px0 = psm[wid][t].x;
                float4 vv = *reinterpret_cast<const float4*>(&vsm[t][4 * lane]);
                float2 px = {px0, px0};
                aS0 = ffma2(px, {vv.x, vv.y}, aS0);
                aS1 = ffma2(px, {vv.z, vv.w}, aS1);
            }
        } else {
#pragma unroll
            for (int t = 0; t < 32; ++t) {
                float py0 = psm[wid][t].y;
                float4 vv = *reinterpret_cast<const float4*>(&vsm[t][4 * lane]);
                float2 py = {py0, py0};
                aW0 = ffma2(py, {vv.x, vv.y}, aW0);
                aW1 = ffma2(py, {vv.z, vv.w}, aW1);
            }
        }
    }

    // ---- finalize ----
    float invS = 1.f / warp_sum(lS);
    float invW = 1.f / warp_sum(lW);
    const float4 c4 = *reinterpret_cast<const float4*>(&g_cmp_o[s][h][4 * lane]);
    float4 o4;
    o4.x = c4.x * gte[0] + aS0.x * invS * gte[1] + aW0.x * invW * gte[2];
    o4.y = c4.y * gte[0] + aS0.y * invS * gte[1] + aW0.y * invW * gte[2];
    o4.z = c4.z * gte[0] + aS1.x * invS * gte[1] + aW1.x * invW * gte[2];
    o4.w = c4.w * gte[0] + aS1.y * invS * gte[1] + aW1.y * invW * gte[2];
    *reinterpret_cast<float4*>(out + ((size_t)s * HQ + h) * D + 4 * lane) = o4;
}

// ============================================================
// launch
// Inputs (metadata order): q, k, v, w_cmp_k, w_cmp_v, w_gate, b_gate
// ============================================================
extern "C" void kernel_launch(void* const* d_in, const int* in_sizes, int n_in,
                              void* d_out, int out_size) {
    const float* q   = (const float*)d_in[0];
    const float* k   = (const float*)d_in[1];
    const float* v   = (const float*)d_in[2];
    const float* wck = (const float*)d_in[3];
    const float* wcv = (const float*)d_in[4];
    const float* wg  = (const float*)d_in[5];
    const float* bg  = (const float*)d_in[6];
    float* out = (float*)d_out;

    k_compress<<<dim3(TBLK, HK), D>>>(k, v, wck, wcv);
    k_cmp_attn<<<S_LEN, HQ * 32>>>(q);
    k_main_attn<<<dim3(S_LEN, HK), 256>>>(q, k, v, wg, bg, out);
}

// round 4
// speedup vs baseline: 2.3994x; 1.5264x over previous
#include <cuda_runtime.h>
#include <math.h>

// ---- NSA hyperparameters (fixed) ----
#define S_LEN 2048
#define HQ 16
#define HK 2
#define GQA 8
#define D 128
#define KS 32
#define ST 16
#define SEL 64
#define TOPN 16
#define WIN 512
#define TBLK 127
#define NSEL 32
#define TQ 8                        // queries per block (q-tile)
#define SCALE 0.08838834764831845f  // 1/sqrt(128)
#define FULLMASK 0xffffffffu
#define KP 132                      // smem K/V row pitch (floats)

// ---- static device scratch ----
__device__ float    g_cmp_k[HK][TBLK][D];
__device__ float    g_cmp_v[HK][TBLK][D];
__device__ float    g_cmp_o[S_LEN][HQ][D];
__device__ unsigned g_sel_mask[HK][S_LEN];

__device__ __forceinline__ float warp_sum(float v) {
#pragma unroll
    for (int o = 16; o; o >>= 1) v += __shfl_xor_sync(FULLMASK, v, o);
    return v;
}
__device__ __forceinline__ float warp_max(float v) {
#pragma unroll
    for (int o = 16; o; o >>= 1) v = fmaxf(v, __shfl_xor_sync(FULLMASK, v, o));
    return v;
}
__device__ __forceinline__ float2 ffma2(float2 a, float2 b, float2 c) {
    unsigned long long au = *reinterpret_cast<unsigned long long*>(&a);
    unsigned long long bu = *reinterpret_cast<unsigned long long*>(&b);
    unsigned long long cu = *reinterpret_cast<unsigned long long*>(&c);
    unsigned long long du;
    asm("fma.rn.f32x2 %0, %1, %2, %3;" : "=l"(du) : "l"(au), "l"(bu), "l"(cu));
    return *reinterpret_cast<float2*>(&du);
}
__device__ __forceinline__ float2 fmul2(float2 a, float2 b) {
    unsigned long long au = *reinterpret_cast<unsigned long long*>(&a);
    unsigned long long bu = *reinterpret_cast<unsigned long long*>(&b);
    unsigned long long du;
    asm("mul.rn.f32x2 %0, %1, %2;" : "=l"(du) : "l"(au), "l"(bu));
    return *reinterpret_cast<float2*>(&du);
}

// ============================================================
// Kernel 1: compressed K/V blocks
// ============================================================
__global__ void k_compress(const float* __restrict__ k,
                           const float* __restrict__ v,
                           const float* __restrict__ wck,
                           const float* __restrict__ wcv) {
    int t = blockIdx.x;
    int n = blockIdx.y;
    int d = threadIdx.x;
    float ak = 0.f, av = 0.f;
#pragma unroll
    for (int w = 0; w < KS; ++w) {
        int j = t * ST + w;
        size_t idx = ((size_t)j * HK + n) * D + d;
        ak += k[idx] * wck[w];
        av += v[idx] * wcv[w];
    }
    g_cmp_k[n][t][d] = ak;
    g_cmp_v[n][t][d] = av;
}

// ============================================================
// Kernel 2: compressed attention + selection, q-tiled.
// Block = (8 queries, n); 8 warps = 8 heads (rows = queries).
// smem: qsm[8q][8h][128], kv tile [32][KP], scb[8h][8q][128].
// Phases: A scores -> B softmax (normalized p in scb) ->
//         C PV (cmp_o) -> D p_slc map + deterministic top-16.
// ============================================================
__global__ void __launch_bounds__(256) k_cmp_sel(const float* __restrict__ q) {
    extern __shared__ float sm[];
    float* qsm = sm;                    // 8192
    float* kv  = sm + 8192;             // 4224
    float* scb = sm + 8192 + 4224;      // 8192

    int s0 = blockIdx.x * TQ;
    int n = blockIdx.y;
    int tid = threadIdx.x;
    int h = tid >> 5;
    int lane = tid & 31;

    // load q tile
    for (int u = tid; u < 2048; u += 256) {
        int qi = u >> 8, rem = u & 255, hh = rem >> 5, d4 = rem & 31;
        *reinterpret_cast<float4*>(qsm + (qi * 8 + hh) * 128 + 4 * d4) =
            *reinterpret_cast<const float4*>(
                q + ((size_t)(s0 + qi) * HQ + n * GQA + hh) * D + 4 * d4);
    }
    int s_max = s0 + TQ - 1;
    int Tvm = (s_max >= KS - 1) ? (s_max - (KS - 1)) / ST + 1 : 0;
    int ct = (Tvm + 31) >> 5;
    __syncthreads();

    // ---- A: raw scores ----
    for (int c = 0; c < ct; ++c) {
        for (int u = tid; u < 1024; u += 256) {
            int row = u >> 5, d4 = u & 31;
            int t = c * 32 + row; if (t > TBLK - 1) t = TBLK - 1;
            *reinterpret_cast<float4*>(kv + row * KP + 4 * d4) =
                *reinterpret_cast<const float4*>(&g_cmp_k[n][t][4 * d4]);
        }
        __syncthreads();
        float2 a2[TQ];
#pragma unroll
        for (int r = 0; r < TQ; ++r) a2[r] = make_float2(0.f, 0.f);
#pragma unroll 8
        for (int d4 = 0; d4 < 32; ++d4) {
            float4 kk = *reinterpret_cast<const float4*>(kv + lane * KP + 4 * d4);
#pragma unroll
            for (int r = 0; r < TQ; ++r) {
                float4 qq = *reinterpret_cast<const float4*>(qsm + (r * 8 + h) * 128 + 4 * d4);
                a2[r] = ffma2({qq.x, qq.y}, {kk.x, kk.y}, a2[r]);
                a2[r] = ffma2({qq.z, qq.w}, {kk.z, kk.w}, a2[r]);
            }
        }
#pragma unroll
        for (int r = 0; r < TQ; ++r)
            scb[(h * 8 + r) * 128 + c * 32 + lane] = (a2[r].x + a2[r].y) * SCALE;
        __syncthreads();
    }

    // ---- B: per-row softmax, normalized p written back ----
#pragma unroll
    for (int r = 0; r < TQ; ++r) {
        int s_r = s0 + r;
        int Tv = (s_r >= KS - 1) ? (s_r - (KS - 1)) / ST + 1 : 0;
        float* row = scb + (h * 8 + r) * 128;
        if (Tv == 0) {
            reinterpret_cast<float4*>(row)[lane] = make_float4(0.f, 0.f, 0.f, 0.f);
            continue;
        }
        float4 v4 = reinterpret_cast<float4*>(row)[lane];
        int tb = 4 * lane;
        float m = fmaxf(fmaxf(tb + 0 < Tv ? v4.x : -INFINITY, tb + 1 < Tv ? v4.y : -INFINITY),
                        fmaxf(tb + 2 < Tv ? v4.z : -INFINITY, tb + 3 < Tv ? v4.w : -INFINITY));
        m = warp_max(m);
        float e0 = tb + 0 < Tv ? __expf(v4.x - m) : 0.f;
        float e1 = tb + 1 < Tv ? __expf(v4.y - m) : 0.f;
        float e2 = tb + 2 < Tv ? __expf(v4.z - m) : 0.f;
        float e3 = tb + 3 < Tv ? __expf(v4.w - m) : 0.f;
        float l = warp_sum(e0 + e1 + e2 + e3);
        float inv = 1.f / l;
        reinterpret_cast<float4*>(row)[lane] =
            make_float4(e0 * inv, e1 * inv, e2 * inv, e3 * inv);
    }
    __syncthreads();

    // ---- C: PV -> g_cmp_o ----
    float2 aC[TQ][2];
#pragma unroll
    for (int r = 0; r < TQ; ++r) { aC[r][0] = {0.f, 0.f}; aC[r][1] = {0.f, 0.f}; }
    for (int c = 0; c < ct; ++c) {
        for (int u = tid; u < 1024; u += 256) {
            int row = u >> 5, d4 = u & 31;
            int t = c * 32 + row; if (t > TBLK - 1) t = TBLK - 1;
            *reinterpret_cast<float4*>(kv + row * KP + 4 * d4) =
                *reinterpret_cast<const float4*>(&g_cmp_v[n][t][4 * d4]);
        }
        __syncthreads();
#pragma unroll 4
        for (int tt = 0; tt < 32; ++tt) {
            int t = c * 32 + tt;
            float4 vv = *reinterpret_cast<const float4*>(kv + tt * KP + 4 * lane);
#pragma unroll
            for (int r = 0; r < TQ; ++r) {
                float p = scb[(h * 8 + r) * 128 + t];
                aC[r][0] = ffma2({p, p}, {vv.x, vv.y}, aC[r][0]);
                aC[r][1] = ffma2({p, p}, {vv.z, vv.w}, aC[r][1]);
            }
        }
        __syncthreads();
    }
#pragma unroll
    for (int r = 0; r < TQ; ++r) {
        float4 o4 = make_float4(aC[r][0].x, aC[r][0].y, aC[r][1].x, aC[r][1].y);
        *reinterpret_cast<float4*>(&g_cmp_o[s0 + r][n * GQA + h][4 * lane]) = o4;
    }

    // ---- D: p_slc + top-16 (warp = query) ----
    {
        int r = h;
        int s_r = s0 + r;
        int m = lane;
        float pm = 0.f;
        int tlo = 4 * m - 1; if (tlo < 0) tlo = 0;
        int thi = 4 * m + 3; if (thi > 127) thi = 127;
        for (int t = tlo; t <= thi; ++t) {
#pragma unroll
            for (int hh = 0; hh < 8; ++hh) pm += scb[(hh * 8 + r) * 128 + t];
        }
        int cur = s_r >> 6;
        bool forced = (m == 0) || (m == cur);
        bool causal = (m <= cur);
        float val = forced ? 1e30f : (causal ? pm : -1e30f);
        unsigned msk = 0;
        for (int it = 0; it < TOPN; ++it) {
            float bv = val;
            int bi = lane;
#pragma unroll
            for (int o = 16; o; o >>= 1) {
                float ov = __shfl_xor_sync(FULLMASK, bv, o);
                int oi = __shfl_xor_sync(FULLMASK, bi, o);
                if (ov > bv || (ov == bv && oi < bi)) { bv = ov; bi = oi; }
            }
            if (bv > -5e29f) msk |= (1u << bi);
            if (lane == bi) val = -INFINITY;
        }
        if (lane == 0) g_sel_mask[n][s_r] = msk;
    }
}

// ============================================================
// Kernel 3: main attention, q-tiled.
// Block = (8 queries, n); 8 warps = heads; warp carries 8 rows
// of dual online-softmax state (shared running max per row).
// Tile list = union over 8 queries of sel | window tiles.
// ============================================================
__global__ void __launch_bounds__(256, 2) k_main_attn(const float* __restrict__ q,
                                                      const float* __restrict__ kg,
                                                      const float* __restrict__ vg,
                                                      const float* __restrict__ wg,
                                                      const float* __restrict__ bg,
                                                      float* __restrict__ out) {
    extern __shared__ float sm[];
    float* qsm = sm;                         // 8192
    float* ksm = sm + 8192;                  // 4224
    float* vsm = sm + 8192 + 4224;           // 4224
    float* psm = sm + 8192 + 8448;           // 8*32*9*2 = 4608 floats
    int*   tli = reinterpret_cast<int*>(sm + 8192 + 8448 + 4608);
    // tli[0..7]=masks, tli[8..71]=tlist, tli[72]=count

    int s0 = (int)(gridDim.x - 1 - blockIdx.x) * TQ;  // long blocks first
    int n = blockIdx.y;
    int tid = threadIdx.x;
    int h = tid >> 5;
    int lane = tid & 31;
    int s_max = s0 + TQ - 1;

    // q tile load
    for (int u = tid; u < 2048; u += 256) {
        int qi = u >> 8, rem = u & 255, hh = rem >> 5, d4 = rem & 31;
        *reinterpret_cast<float4*>(qsm + (qi * 8 + hh) * 128 + 4 * d4) =
            *reinterpret_cast<const float4*>(
                q + ((size_t)(s0 + qi) * HQ + n * GQA + hh) * D + 4 * d4);
    }
    // tile list (thread 0)
    if (tid == 0) {
        unsigned orm = 0;
#pragma unroll
        for (int r = 0; r < TQ; ++r) {
            unsigned mk = g_sel_mask[n][s0 + r];
            tli[r] = (int)mk;
            orm |= mk;
        }
        int winlo0 = s0 - WIN; if (winlo0 < 0) winlo0 = 0;
        int cur_max = s_max >> 6;
        int c = 0;
        for (int b = 0; b <= cur_max; ++b) {
            bool anysel = (orm >> b) & 1u;
            for (int half = 0; half < 2; ++half) {
                int t0 = (b << 6) + half * 32;
                if (t0 > s_max) break;
                if (anysel || (t0 + 31 >= winlo0)) tli[8 + c++] = t0;
            }
        }
        tli[72] = c;
    }
    __syncthreads();
    int nt = tli[72];

    float m[TQ], lS[TQ], lW[TQ];
    float2 aS[TQ][2], aW[TQ][2];
#pragma unroll
    for (int r = 0; r < TQ; ++r) {
        m[r] = -INFINITY; lS[r] = 0.f; lW[r] = 0.f;
        aS[r][0] = {0.f, 0.f}; aS[r][1] = {0.f, 0.f};
        aW[r][0] = {0.f, 0.f}; aW[r][1] = {0.f, 0.f};
    }

    for (int i = 0; i < nt; ++i) {
        int t0 = tli[8 + i];
        __syncthreads();
        for (int u = tid; u < 1024; u += 256) {
            int row = u >> 5, d4 = u & 31;
            size_t gi = ((size_t)(t0 + row) * HK + n) * D + 4 * d4;
            *reinterpret_cast<float4*>(ksm + row * KP + 4 * d4) =
                *reinterpret_cast<const float4*>(kg + gi);
            *reinterpret_cast<float4*>(vsm + row * KP + 4 * d4) =
                *reinterpret_cast<const float4*>(vg + gi);
        }
        __syncthreads();

        // per-row flags
        int b = t0 >> 6;
        int selb = 0, winb = 0;
#pragma unroll
        for (int r = 0; r < TQ; ++r) {
            int s_r = s0 + r;
            int wl = s_r - WIN; if (wl < 0) wl = 0;
            bool ok = (t0 <= s_r);
            if (ok && (((unsigned)tli[r] >> b) & 1u)) selb |= 1 << r;
            if (ok && (t0 + 31 >= wl)) winb |= 1 << r;
        }
        int actb = selb | winb;
        int j = t0 + lane;

        // ---- scores ----
        float2 a2[TQ];
#pragma unroll
        for (int r = 0; r < TQ; ++r) a2[r] = make_float2(0.f, 0.f);
#pragma unroll 8
        for (int d4 = 0; d4 < 32; ++d4) {
            float4 kk = *reinterpret_cast<const float4*>(ksm + lane * KP + 4 * d4);
#pragma unroll
            for (int r = 0; r < TQ; ++r) {
                float4 qq = *reinterpret_cast<const float4*>(qsm + (r * 8 + h) * 128 + 4 * d4);
                a2[r] = ffma2({qq.x, qq.y}, {kk.x, kk.y}, a2[r]);
                a2[r] = ffma2({qq.z, qq.w}, {kk.z, kk.w}, a2[r]);
            }
        }

        // ---- dual online-softmax (shared max), write p to psm ----
#pragma unroll
        for (int r = 0; r < TQ; ++r) {
            if (!((actb >> r) & 1)) continue;
            int s_r = s0 + r;
            int wl = s_r - WIN; if (wl < 0) wl = 0;
            bool ins = (selb >> r) & 1;
            float sc = (a2[r].x + a2[r].y) * SCALE;
            bool contrib = (j <= s_r) && (ins || (j >= wl));
            float tm = warp_max(contrib ? sc : -INFINITY);
            float nm = fmaxf(m[r], tm);
            float al = __expf(m[r] - nm);
            m[r] = nm;
            float pe = contrib ? __expf(sc - nm) : 0.f;
            float pS = ins ? pe : 0.f;
            float pW = (j >= wl) ? pe : 0.f;
            lS[r] = lS[r] * al + pS;
            lW[r] = lW[r] * al + pW;
            float2 al2 = {al, al};
            aS[r][0] = fmul2(aS[r][0], al2); aS[r][1] = fmul2(aS[r][1], al2);
            aW[r][0] = fmul2(aW[r][0], al2); aW[r][1] = fmul2(aW[r][1], al2);
            *reinterpret_cast<float2*>(psm + ((h * 32 + lane) * 9 + r) * 2) =
                make_float2(pS, pW);
        }
        __syncwarp();

        // ---- PV: lane = d-quad ----
#pragma unroll 4
        for (int tt = 0; tt < 32; ++tt) {
            float4 vv = *reinterpret_cast<const float4*>(vsm + tt * KP + 4 * lane);
            float2 va = {vv.x, vv.y}, vb = {vv.z, vv.w};
#pragma unroll
            for (int rp = 0; rp < 4; ++rp) {
                float4 pq = *reinterpret_cast<const float4*>(psm + ((h * 32 + tt) * 9 + 2 * rp) * 2);
                int r0 = 2 * rp, r1 = r0 + 1;
                if ((selb >> r0) & 1) {
                    aS[r0][0] = ffma2({pq.x, pq.x}, va, aS[r0][0]);
                    aS[r0][1] = ffma2({pq.x, pq.x}, vb, aS[r0][1]);
                }
                if ((winb >> r0) & 1) {
                    aW[r0][0] = ffma2({pq.y, pq.y}, va, aW[r0][0]);
                    aW[r0][1] = ffma2({pq.y, pq.y}, vb, aW[r0][1]);
                }
                if ((selb >> r1) & 1) {
                    aS[r1][0] = ffma2({pq.z, pq.z}, va, aS[r1][0]);
                    aS[r1][1] = ffma2({pq.z, pq.z}, vb, aS[r1][1]);
                }
                if ((winb >> r1) & 1) {
                    aW[r1][0] = ffma2({pq.w, pq.w}, va, aW[r1][0]);
                    aW[r1][1] = ffma2({pq.w, pq.w}, vb, aW[r1][1]);
                }
            }
        }
    }

    // ---- finalize: gates + combine ----
#pragma unroll
    for (int r = 0; r < TQ; ++r) {
        int s_r = s0 + r;
        float4 q4 = *reinterpret_cast<const float4*>(qsm + (r * 8 + h) * 128 + 4 * lane);
        float gt[3];
#pragma unroll
        for (int c = 0; c < 3; ++c) {
            float gp = q4.x * wg[(4 * lane + 0) * 3 + c]
                     + q4.y * wg[(4 * lane + 1) * 3 + c]
                     + q4.z * wg[(4 * lane + 2) * 3 + c]
                     + q4.w * wg[(4 * lane + 3) * 3 + c];
            gp = warp_sum(gp) + bg[c];
            gt[c] = 1.f / (1.f + __expf(-gp));
        }
        float iS = 1.f / warp_sum(lS[r]);
        float iW = 1.f / warp_sum(lW[r]);
        float4 c4 = *reinterpret_cast<const float4*>(&g_cmp_o[s_r][n * GQA + h][4 * lane]);
        float4 o4;
        o4.x = c4.x * gt[0] + aS[r][0].x * iS * gt[1] + aW[r][0].x * iW * gt[2];
        o4.y = c4.y * gt[0] + aS[r][0].y * iS * gt[1] + aW[r][0].y * iW * gt[2];
        o4.z = c4.z * gt[0] + aS[r][1].x * iS * gt[1] + aW[r][1].x * iW * gt[2];
        o4.w = c4.w * gt[0] + aS[r][1].y * iS * gt[1] + aW[r][1].y * iW * gt[2];
        *reinterpret_cast<float4*>(out + ((size_t)s_r * HQ + n * GQA + h) * D + 4 * lane) = o4;
    }
}

// ============================================================
// launch  (inputs: q, k, v, w_cmp_k, w_cmp_v, w_gate, b_gate)
// ============================================================
extern "C" void kernel_launch(void* const* d_in, const int* in_sizes, int n_in,
                              void* d_out, int out_size) {
    const float* q   = (const float*)d_in[0];
    const float* k   = (const float*)d_in[1];
    const float* v   = (const float*)d_in[2];
    const float* wck = (const float*)d_in[3];
    const float* wcv = (const float*)d_in[4];
    const float* wg  = (const float*)d_in[5];
    const float* bg  = (const float*)d_in[6];
    float* out = (float*)d_out;

    const int smem2 = (8192 + 4224 + 8192) * 4;
    const int smem3 = (8192 + 4224 + 4224 + 4608) * 4 + 73 * 4;
    cudaFuncSetAttribute(k_cmp_sel, cudaFuncAttributeMaxDynamicSharedMemorySize, smem2);
    cudaFuncSetAttribute(k_main_attn, cudaFuncAttributeMaxDynamicSharedMemorySize, smem3);

    k_compress<<<dim3(TBLK, HK), D>>>(k, v, wck, wcv);
    k_cmp_sel<<<dim3(S_LEN / TQ, HK), 256, smem2>>>(q);
    k_main_attn<<<dim3(S_LEN / TQ, HK), 256, smem3>>>(q, k, v, wg, bg, out);
}

// round 5
// speedup vs baseline: 2.6058x; 1.0860x over previous
#include <cuda_runtime.h>
#include <math.h>

// ---- NSA hyperparameters (fixed) ----
#define S_LEN 2048
#define HQ 16
#define HK 2
#define GQA 8
#define D 128
#define KS 32
#define ST 16
#define SEL 64
#define TOPN 16
#define WIN 512
#define TBLK 127
#define NSEL 32
#define TQ 8                        // queries per block (q-tile)
#define SCALE 0.08838834764831845f  // 1/sqrt(128)
#define FULLMASK 0xffffffffu
#define KP 132                      // smem K/V row pitch (floats)

// ---- static device scratch ----
__device__ float    g_cmp_k[HK][TBLK][D];
__device__ float    g_cmp_v[HK][TBLK][D];
__device__ float    g_cmp_o[S_LEN][HQ][D];
__device__ unsigned g_sel_mask[HK][S_LEN];

__device__ __forceinline__ float warp_sum(float v) {
#pragma unroll
    for (int o = 16; o; o >>= 1) v += __shfl_xor_sync(FULLMASK, v, o);
    return v;
}
__device__ __forceinline__ float warp_max(float v) {
#pragma unroll
    for (int o = 16; o; o >>= 1) v = fmaxf(v, __shfl_xor_sync(FULLMASK, v, o));
    return v;
}
__device__ __forceinline__ float2 ffma2(float2 a, float2 b, float2 c) {
    unsigned long long au = *reinterpret_cast<unsigned long long*>(&a);
    unsigned long long bu = *reinterpret_cast<unsigned long long*>(&b);
    unsigned long long cu = *reinterpret_cast<unsigned long long*>(&c);
    unsigned long long du;
    asm("fma.rn.f32x2 %0, %1, %2, %3;" : "=l"(du) : "l"(au), "l"(bu), "l"(cu));
    return *reinterpret_cast<float2*>(&du);
}
__device__ __forceinline__ float2 fmul2(float2 a, float2 b) {
    unsigned long long au = *reinterpret_cast<unsigned long long*>(&a);
    unsigned long long bu = *reinterpret_cast<unsigned long long*>(&b);
    unsigned long long du;
    asm("mul.rn.f32x2 %0, %1, %2;" : "=l"(du) : "l"(au), "l"(bu));
    return *reinterpret_cast<float2*>(&du);
}
__device__ __forceinline__ void cp_async16(float* smem_dst, const float* gmem_src) {
    unsigned sa = (unsigned)__cvta_generic_to_shared(smem_dst);
    asm volatile("cp.async.cg.shared.global [%0], [%1], 16;\n" :: "r"(sa), "l"(gmem_src));
}
#define CP_COMMIT()  asm volatile("cp.async.commit_group;\n" ::: "memory")
#define CP_WAIT(N)   asm volatile("cp.async.wait_group %0;\n" :: "n"(N) : "memory")

// ============================================================
// Kernel 1: compressed K/V blocks
// ============================================================
__global__ void k_compress(const float* __restrict__ k,
                           const float* __restrict__ v,
                           const float* __restrict__ wck,
                           const float* __restrict__ wcv) {
    int t = blockIdx.x;
    int n = blockIdx.y;
    int d = threadIdx.x;
    float ak = 0.f, av = 0.f;
#pragma unroll
    for (int w = 0; w < KS; ++w) {
        int j = t * ST + w;
        size_t idx = ((size_t)j * HK + n) * D + d;
        ak += k[idx] * wck[w];
        av += v[idx] * wcv[w];
    }
    g_cmp_k[n][t][d] = ak;
    g_cmp_v[n][t][d] = av;
}

// ============================================================
// Kernel 2: compressed attention + selection, q-tiled.
// ============================================================
__global__ void __launch_bounds__(256) k_cmp_sel(const float* __restrict__ q) {
    extern __shared__ float sm[];
    float* qsm = sm;                    // 8192
    float* kv  = sm + 8192;             // 4224
    float* scb = sm + 8192 + 4224;      // 8192

    int s0 = blockIdx.x * TQ;
    int n = blockIdx.y;
    int tid = threadIdx.x;
    int h = tid >> 5;
    int lane = tid & 31;

    for (int u = tid; u < 2048; u += 256) {
        int qi = u >> 8, rem = u & 255, hh = rem >> 5, d4 = rem & 31;
        *reinterpret_cast<float4*>(qsm + (qi * 8 + hh) * 128 + 4 * d4) =
            *reinterpret_cast<const float4*>(
                q + ((size_t)(s0 + qi) * HQ + n * GQA + hh) * D + 4 * d4);
    }
    int s_max = s0 + TQ - 1;
    int Tvm = (s_max >= KS - 1) ? (s_max - (KS - 1)) / ST + 1 : 0;
    int ct = (Tvm + 31) >> 5;
    __syncthreads();

    // ---- A: raw scores ----
    for (int c = 0; c < ct; ++c) {
        for (int u = tid; u < 1024; u += 256) {
            int row = u >> 5, d4 = u & 31;
            int t = c * 32 + row; if (t > TBLK - 1) t = TBLK - 1;
            *reinterpret_cast<float4*>(kv + row * KP + 4 * d4) =
                *reinterpret_cast<const float4*>(&g_cmp_k[n][t][4 * d4]);
        }
        __syncthreads();
        float2 a2[TQ];
#pragma unroll
        for (int r = 0; r < TQ; ++r) a2[r] = make_float2(0.f, 0.f);
#pragma unroll 8
        for (int d4 = 0; d4 < 32; ++d4) {
            float4 kk = *reinterpret_cast<const float4*>(kv + lane * KP + 4 * d4);
#pragma unroll
            for (int r = 0; r < TQ; ++r) {
                float4 qq = *reinterpret_cast<const float4*>(qsm + (r * 8 + h) * 128 + 4 * d4);
                a2[r] = ffma2({qq.x, qq.y}, {kk.x, kk.y}, a2[r]);
                a2[r] = ffma2({qq.z, qq.w}, {kk.z, kk.w}, a2[r]);
            }
        }
#pragma unroll
        for (int r = 0; r < TQ; ++r)
            scb[(h * 8 + r) * 128 + c * 32 + lane] = (a2[r].x + a2[r].y) * SCALE;
        __syncthreads();
    }

    // ---- B: per-row softmax ----
#pragma unroll
    for (int r = 0; r < TQ; ++r) {
        int s_r = s0 + r;
        int Tv = (s_r >= KS - 1) ? (s_r - (KS - 1)) / ST + 1 : 0;
        float* row = scb + (h * 8 + r) * 128;
        if (Tv == 0) {
            reinterpret_cast<float4*>(row)[lane] = make_float4(0.f, 0.f, 0.f, 0.f);
            continue;
        }
        float4 v4 = reinterpret_cast<float4*>(row)[lane];
        int tb = 4 * lane;
        float m = fmaxf(fmaxf(tb + 0 < Tv ? v4.x : -INFINITY, tb + 1 < Tv ? v4.y : -INFINITY),
                        fmaxf(tb + 2 < Tv ? v4.z : -INFINITY, tb + 3 < Tv ? v4.w : -INFINITY));
        m = warp_max(m);
        float e0 = tb + 0 < Tv ? __expf(v4.x - m) : 0.f;
        float e1 = tb + 1 < Tv ? __expf(v4.y - m) : 0.f;
        float e2 = tb + 2 < Tv ? __expf(v4.z - m) : 0.f;
        float e3 = tb + 3 < Tv ? __expf(v4.w - m) : 0.f;
        float l = warp_sum(e0 + e1 + e2 + e3);
        float inv = 1.f / l;
        reinterpret_cast<float4*>(row)[lane] =
            make_float4(e0 * inv, e1 * inv, e2 * inv, e3 * inv);
    }
    __syncthreads();

    // ---- C: PV -> g_cmp_o ----
    float2 aC[TQ][2];
#pragma unroll
    for (int r = 0; r < TQ; ++r) { aC[r][0] = {0.f, 0.f}; aC[r][1] = {0.f, 0.f}; }
    for (int c = 0; c < ct; ++c) {
        for (int u = tid; u < 1024; u += 256) {
            int row = u >> 5, d4 = u & 31;
            int t = c * 32 + row; if (t > TBLK - 1) t = TBLK - 1;
            *reinterpret_cast<float4*>(kv + row * KP + 4 * d4) =
                *reinterpret_cast<const float4*>(&g_cmp_v[n][t][4 * d4]);
        }
        __syncthreads();
#pragma unroll 4
        for (int tt = 0; tt < 32; ++tt) {
            int t = c * 32 + tt;
            float4 vv = *reinterpret_cast<const float4*>(kv + tt * KP + 4 * lane);
#pragma unroll
            for (int r = 0; r < TQ; ++r) {
                float p = scb[(h * 8 + r) * 128 + t];
                aC[r][0] = ffma2({p, p}, {vv.x, vv.y}, aC[r][0]);
                aC[r][1] = ffma2({p, p}, {vv.z, vv.w}, aC[r][1]);
            }
        }
        __syncthreads();
    }
#pragma unroll
    for (int r = 0; r < TQ; ++r) {
        float4 o4 = make_float4(aC[r][0].x, aC[r][0].y, aC[r][1].x, aC[r][1].y);
        *reinterpret_cast<float4*>(&g_cmp_o[s0 + r][n * GQA + h][4 * lane]) = o4;
    }

    // ---- D: p_slc + top-16 (warp = query) ----
    {
        int r = h;
        int s_r = s0 + r;
        int m = lane;
        float pm = 0.f;
        int tlo = 4 * m - 1; if (tlo < 0) tlo = 0;
        int thi = 4 * m + 3; if (thi > 127) thi = 127;
        for (int t = tlo; t <= thi; ++t) {
#pragma unroll
            for (int hh = 0; hh < 8; ++hh) pm += scb[(hh * 8 + r) * 128 + t];
        }
        int cur = s_r >> 6;
        bool forced = (m == 0) || (m == cur);
        bool causal = (m <= cur);
        float val = forced ? 1e30f : (causal ? pm : -1e30f);
        unsigned msk = 0;
        for (int it = 0; it < TOPN; ++it) {
            float bv = val;
            int bi = lane;
#pragma unroll
            for (int o = 16; o; o >>= 1) {
                float ov = __shfl_xor_sync(FULLMASK, bv, o);
                int oi = __shfl_xor_sync(FULLMASK, bi, o);
                if (ov > bv || (ov == bv && oi < bi)) { bv = ov; bi = oi; }
            }
            if (bv > -5e29f) msk |= (1u << bi);
            if (lane == bi) val = -INFINITY;
        }
        if (lane == 0) g_sel_mask[n][s_r] = msk;
    }
}

// ============================================================
// Kernel 3: main attention, q-tiled + cp.async pipelined.
// K double-buffered (consumed next iter), V single-buffered
// (waited after score phase). Groups per iter: [V(i)],[K(i+1)].
// ============================================================
__global__ void __launch_bounds__(256, 2) k_main_attn(const float* __restrict__ q,
                                                      const float* __restrict__ kg,
                                                      const float* __restrict__ vg,
                                                      const float* __restrict__ wg,
                                                      const float* __restrict__ bg,
                                                      float* __restrict__ out) {
    extern __shared__ float sm[];
    float* qsm  = sm;                         // 8192
    float* ksm0 = sm + 8192;                  // 4224
    float* ksm1 = sm + 8192 + 4224;           // 4224
    float* vsm  = sm + 8192 + 8448;           // 4224
    float* psm  = sm + 8192 + 12672;          // 4608
    int*   tli  = reinterpret_cast<int*>(sm + 8192 + 12672 + 4608);
    // tli[0..7]=masks, tli[8..71]=tlist, tli[72]=count

    int s0 = (int)(gridDim.x - 1 - blockIdx.x) * TQ;  // long blocks first
    int n = blockIdx.y;
    int tid = threadIdx.x;
    int h = tid >> 5;
    int lane = tid & 31;
    int s_max = s0 + TQ - 1;

    // staging geometry for this thread: 4 (row, d4) pairs
    int st_row = tid >> 5;        // rows h, h+8, h+16, h+24
    int st_d4 = tid & 31;

    for (int u = tid; u < 2048; u += 256) {
        int qi = u >> 8, rem = u & 255, hh = rem >> 5, d4 = rem & 31;
        *reinterpret_cast<float4*>(qsm + (qi * 8 + hh) * 128 + 4 * d4) =
            *reinterpret_cast<const float4*>(
                q + ((size_t)(s0 + qi) * HQ + n * GQA + hh) * D + 4 * d4);
    }
    if (tid == 0) {
        unsigned orm = 0;
#pragma unroll
        for (int r = 0; r < TQ; ++r) {
            unsigned mk = g_sel_mask[n][s0 + r];
            tli[r] = (int)mk;
            orm |= mk;
        }
        int winlo0 = s0 - WIN; if (winlo0 < 0) winlo0 = 0;
        int cur_max = s_max >> 6;
        int c = 0;
        for (int b = 0; b <= cur_max; ++b) {
            bool anysel = (orm >> b) & 1u;
            for (int half = 0; half < 2; ++half) {
                int t0 = (b << 6) + half * 32;
                if (t0 > s_max) break;
                if (anysel || (t0 + 31 >= winlo0)) tli[8 + c++] = t0;
            }
        }
        tli[72] = c;
    }
    __syncthreads();
    int nt = tli[72];

    float m[TQ], lS[TQ], lW[TQ];
    float2 aS[TQ][2], aW[TQ][2];
#pragma unroll
    for (int r = 0; r < TQ; ++r) {
        m[r] = -INFINITY; lS[r] = 0.f; lW[r] = 0.f;
        aS[r][0] = {0.f, 0.f}; aS[r][1] = {0.f, 0.f};
        aW[r][0] = {0.f, 0.f}; aW[r][1] = {0.f, 0.f};
    }

    // ---- prologue: prefetch K(0) ----
    if (nt > 0) {
        int t0 = tli[8];
#pragma unroll
        for (int rr = 0; rr < 4; ++rr) {
            int row = st_row + 8 * rr;
            cp_async16(ksm0 + row * KP + 4 * st_d4,
                       kg + ((size_t)(t0 + row) * HK + n) * D + 4 * st_d4);
        }
    }
    CP_COMMIT();   // group: K(0)

    for (int i = 0; i < nt; ++i) {
        int t0 = tli[8 + i];
        float* kcur = (i & 1) ? ksm1 : ksm0;
        float* knxt = (i & 1) ? ksm0 : ksm1;

        __syncthreads();   // S1: vsm free (PV(i-1) done), knxt free (scores(i-1) done)

        // V(i) -> vsm  (own group)
#pragma unroll
        for (int rr = 0; rr < 4; ++rr) {
            int row = st_row + 8 * rr;
            cp_async16(vsm + row * KP + 4 * st_d4,
                       vg + ((size_t)(t0 + row) * HK + n) * D + 4 * st_d4);
        }
        CP_COMMIT();   // group: V(i)

        // K(i+1) -> knxt (own group; empty group when none to keep counts uniform)
        if (i + 1 < nt) {
            int t0n = tli[8 + i + 1];
#pragma unroll
            for (int rr = 0; rr < 4; ++rr) {
                int row = st_row + 8 * rr;
                cp_async16(knxt + row * KP + 4 * st_d4,
                           kg + ((size_t)(t0n + row) * HK + n) * D + 4 * st_d4);
            }
        }
        CP_COMMIT();   // group: K(i+1)

        CP_WAIT(2);        // K(i) arrived
        __syncthreads();   // S2: K(i) visible to all warps

        // per-row flags
        int b = t0 >> 6;
        int selb = 0, winb = 0;
#pragma unroll
        for (int r = 0; r < TQ; ++r) {
            int s_r = s0 + r;
            int wl = s_r - WIN; if (wl < 0) wl = 0;
            bool ok = (t0 <= s_r);
            if (ok && (((unsigned)tli[r] >> b) & 1u)) selb |= 1 << r;
            if (ok && (t0 + 31 >= wl)) winb |= 1 << r;
        }
        int actb = selb | winb;
        int j = t0 + lane;

        // ---- scores ----
        float2 a2[TQ];
#pragma unroll
        for (int r = 0; r < TQ; ++r) a2[r] = make_float2(0.f, 0.f);
#pragma unroll 8
        for (int d4 = 0; d4 < 32; ++d4) {
            float4 kk = *reinterpret_cast<const float4*>(kcur + lane * KP + 4 * d4);
#pragma unroll
            for (int r = 0; r < TQ; ++r) {
                float4 qq = *reinterpret_cast<const float4*>(qsm + (r * 8 + h) * 128 + 4 * d4);
                a2[r] = ffma2({qq.x, qq.y}, {kk.x, kk.y}, a2[r]);
                a2[r] = ffma2({qq.z, qq.w}, {kk.z, kk.w}, a2[r]);
            }
        }

        // ---- dual online-softmax (shared max), p -> psm ----
#pragma unroll
        for (int r = 0; r < TQ; ++r) {
            if (!((actb >> r) & 1)) continue;
            int s_r = s0 + r;
            int wl = s_r - WIN; if (wl < 0) wl = 0;
            bool ins = (selb >> r) & 1;
            float sc = (a2[r].x + a2[r].y) * SCALE;
            bool contrib = (j <= s_r) && (ins || (j >= wl));
            float tm = warp_max(contrib ? sc : -INFINITY);
            float nm = fmaxf(m[r], tm);
            float al = __expf(m[r] - nm);
            m[r] = nm;
            float pe = contrib ? __expf(sc - nm) : 0.f;
            float pS = ins ? pe : 0.f;
            float pW = (j >= wl) ? pe : 0.f;
            lS[r] = lS[r] * al + pS;
            lW[r] = lW[r] * al + pW;
            float2 al2 = {al, al};
            aS[r][0] = fmul2(aS[r][0], al2); aS[r][1] = fmul2(aS[r][1], al2);
            aW[r][0] = fmul2(aW[r][0], al2); aW[r][1] = fmul2(aW[r][1], al2);
            *reinterpret_cast<float2*>(psm + ((h * 32 + lane) * 9 + r) * 2) =
                make_float2(pS, pW);
        }
        __syncwarp();

        CP_WAIT(1);        // V(i) arrived (K(i+1) may still be in flight)
        __syncthreads();   // S3: V(i) visible

        // ---- PV: lane = d-quad ----
#pragma unroll 4
        for (int tt = 0; tt < 32; ++tt) {
            float4 vv = *reinterpret_cast<const float4*>(vsm + tt * KP + 4 * lane);
            float2 va = {vv.x, vv.y}, vb = {vv.z, vv.w};
#pragma unroll
            for (int rp = 0; rp < 4; ++rp) {
                float4 pq = *reinterpret_cast<const float4*>(psm + ((h * 32 + tt) * 9 + 2 * rp) * 2);
                int r0 = 2 * rp, r1 = r0 + 1;
                if ((selb >> r0) & 1) {
                    aS[r0][0] = ffma2({pq.x, pq.x}, va, aS[r0][0]);
                    aS[r0][1] = ffma2({pq.x, pq.x}, vb, aS[r0][1]);
                }
                if ((winb >> r0) & 1) {
                    aW[r0][0] = ffma2({pq.y, pq.y}, va, aW[r0][0]);
                    aW[r0][1] = ffma2({pq.y, pq.y}, vb, aW[r0][1]);
                }
                if ((selb >> r1) & 1) {
                    aS[r1][0] = ffma2({pq.z, pq.z}, va, aS[r1][0]);
                    aS[r1][1] = ffma2({pq.z, pq.z}, vb, aS[r1][1]);
                }
                if ((winb >> r1) & 1) {
                    aW[r1][0] = ffma2({pq.w, pq.w}, va, aW[r1][0]);
                    aW[r1][1] = ffma2({pq.w, pq.w}, vb, aW[r1][1]);
                }
            }
        }
    }

    // ---- finalize: gates + combine ----
#pragma unroll
    for (int r = 0; r < TQ; ++r) {
        int s_r = s0 + r;
        float4 q4 = *reinterpret_cast<const float4*>(qsm + (r * 8 + h) * 128 + 4 * lane);
        float gt[3];
#pragma unroll
        for (int c = 0; c < 3; ++c) {
            float gp = q4.x * wg[(4 * lane + 0) * 3 + c]
                     + q4.y * wg[(4 * lane + 1) * 3 + c]
                     + q4.z * wg[(4 * lane + 2) * 3 + c]
                     + q4.w * wg[(4 * lane + 3) * 3 + c];
            gp = warp_sum(gp) + bg[c];
            gt[c] = 1.f / (1.f + __expf(-gp));
        }
        float iS = 1.f / warp_sum(lS[r]);
        float iW = 1.f / warp_sum(lW[r]);
        float4 c4 = *reinterpret_cast<const float4*>(&g_cmp_o[s_r][n * GQA + h][4 * lane]);
        float4 o4;
        o4.x = c4.x * gt[0] + aS[r][0].x * iS * gt[1] + aW[r][0].x * iW * gt[2];
        o4.y = c4.y * gt[0] + aS[r][0].y * iS * gt[1] + aW[r][0].y * iW * gt[2];
        o4.z = c4.z * gt[0] + aS[r][1].x * iS * gt[1] + aW[r][1].x * iW * gt[2];
        o4.w = c4.w * gt[0] + aS[r][1].y * iS * gt[1] + aW[r][1].y * iW * gt[2];
        *reinterpret_cast<float4*>(out + ((size_t)s_r * HQ + n * GQA + h) * D + 4 * lane) = o4;
    }
}

// ============================================================
// launch  (inputs: q, k, v, w_cmp_k, w_cmp_v, w_gate, b_gate)
// ============================================================
extern "C" void kernel_launch(void* const* d_in, const int* in_sizes, int n_in,
                              void* d_out, int out_size) {
    const float* q   = (const float*)d_in[0];
    const float* k   = (const float*)d_in[1];
    const float* v   = (const float*)d_in[2];
    const float* wck = (const float*)d_in[3];
    const float* wcv = (const float*)d_in[4];
    const float* wg  = (const float*)d_in[5];
    const float* bg  = (const float*)d_in[6];
    float* out = (float*)d_out;

    const int smem2 = (8192 + 4224 + 8192) * 4;
    const int smem3 = (8192 + 4224 * 3 + 4608) * 4 + 73 * 4;
    cudaFuncSetAttribute(k_cmp_sel, cudaFuncAttributeMaxDynamicSharedMemorySize, smem2);
    cudaFuncSetAttribute(k_main_attn, cudaFuncAttributeMaxDynamicSharedMemorySize, smem3);

    k_compress<<<dim3(TBLK, HK), D>>>(k, v, wck, wcv);
    k_cmp_sel<<<dim3(S_LEN / TQ, HK), 256, smem2>>>(q);
    k_main_attn<<<dim3(S_LEN / TQ, HK), 256, smem3>>>(q, k, v, wg, bg, out);
}